// round 10
// baseline (speedup 1.0000x reference)
#include <cuda_runtime.h>
#include <cstdint>

#define BB      48
#define NKC     800
#define NMBON   20
#define NFBN    60
#define NDAN    20
#define NREC    100
#define TT      121
#define NSTEP   120
#define W_MAXC  0.05f

#define NTHREADS 512

__device__ float g_rkcT[(long)BB * TT * NKC];

// ---------------------------------------------------------------------------
// Transpose r_kc [B, NKC, T] -> g_rkcT [B, T, NKC]
// ---------------------------------------------------------------------------
__global__ void transpose_kernel(const float* __restrict__ rkc) {
    __shared__ float tile[32][33];
    const int bz = blockIdx.z;
    const int kt = blockIdx.y;
    const int tt = blockIdx.x;
    const int tx = threadIdx.x, ty = threadIdx.y;

    int k = kt * 32 + ty;
    int t = tt * 32 + tx;
    if (t < TT)
        tile[ty][tx] = rkc[((long)bz * NKC + k) * TT + t];
    __syncthreads();
    int t2 = tt * 32 + ty;
    int k2 = kt * 32 + tx;
    if (t2 < TT)
        g_rkcT[((long)bz * TT + t2) * NKC + k2] = tile[tx][ty];
}

// ---------------------------------------------------------------------------
// PASS 1: r-dynamics only. ONE CTA per batch (no cluster, no exchange).
// Owners: q = tid&255 < 200 (400 threads), g = tid>>8 picks rows g*10..g*10+9,
//   chunk q (float4 k=4q). W/wt/rb_kc all in registers.
// Warp roles (pre-bar1 / post-bar1):
//   full owner warps (0-5, 8-13): B(t) 5-round reduce / D(t)
//   warps 6,14 lanes 0-7: B(t) 3-round (mask 0xFF) / D(t)
//   warp 6 lanes 8-15 (tid 200-207):  idle / dot i=64..71
//   warp 14 lane 8 (tid 456):         readout(t) / dot i=72
//   warp 14 lanes 8-15 (456-463):     - / dots i=72..79
//   warp 7 (224-255): DAN half-dots idx 0-31 / dots i=0..31
//   warp 15 lanes 0-7 (480-487): DAN half-dots idx 32-39 / dots i=32..39
//   warp 15 lanes 8-31 (488-511): cp.async + ifbn / dots i=40..63 + cp wait
// ---------------------------------------------------------------------------
// smem floats: WrM 10000 | rkc3 2400 | r 200 | bias 100 | ifbn 128 |
//              red 140 | rdan 20 | rbdan 20 | wro 20 | wext 120
#define SM_FLOATS (10000 + 2400 + 200 + 100 + 128 + 140 + 20 + 20 + 20 + 120)

__global__ __launch_bounds__(NTHREADS, 1)
void rnn_kernel(
    const float* __restrict__ r_ext,
    const float* __restrict__ time_arr,
    const float* __restrict__ W_kc0,
    const float* __restrict__ wt0,
    const float* __restrict__ W_recur,
    const float* __restrict__ W_readout,
    const float* __restrict__ bias,
    const float* __restrict__ W_ext,
    float* __restrict__ out)
{
    extern __shared__ float sm[];
    float* WrM     = sm;                  // 100 x 100 row-major (rows<20: cols 80-99 zeroed)
    float* rkc3    = sm + 10000;          // 3 x 800 ring
    float* r_s     = sm + 12400;          // 2 x 100
    float* bias_s  = sm + 12600;          // 100
    float* ifbn    = sm + 12700;          // 2 x 64
    float* red_s   = sm + 12828;          // 7 slots x 20 rows
    float* rdan_s  = sm + 12968;          // 20
    float* rbdan_s = sm + 12988;          // 20
    float* wro_s   = sm + 13008;          // 20
    float* wext_s  = sm + 13028;          // 120

    const int tid  = threadIdx.x;
    const int b    = blockIdx.x;
    const int lane = tid & 31;
    const int warp = tid >> 5;
    const int g    = tid >> 8;            // 0/1 -> rows g*10..g*10+9
    const int q    = tid & 255;
    const bool owner = (q < 200);

    // DAN half-split assignment
    const bool is_dan = (tid >= 224 && tid < 256) || (tid >= 480 && tid < 488);
    const int  didx   = (tid < 256) ? (tid - 224) : (32 + tid - 480);   // 0..39
    const int  drow   = 80 + (didx >> 1);
    const int  dh     = didx & 1;
    const unsigned dmask = (tid < 256) ? 0xffffffffu : 0x000000ffu;

    // staging
    const bool is_stage = (tid >= 488);
    const int  sl = tid - 488;            // 0..23

    // post-bar1 dot assignment
    int di = -1;
    if (tid >= 224 && tid < 256)       di = tid - 224;         // 0..31
    else if (tid >= 480)               di = 32 + (tid - 480);  // 32..63
    else if (tid >= 200 && tid < 208)  di = 64 + (tid - 200);  // 64..71
    else if (tid >= 456 && tid < 464)  di = 72 + (tid - 456);  // 72..79

    float* out_r  = out;
    float* out_ro = out + (long)TT * BB * NREC + 2L * TT * BB * NMBON * NKC;

    const float dt  = time_arr[1] - time_arr[0];
    const float a_r = dt;
    const float a_w = dt * 0.2f;

    const float* rkc_g = g_rkcT + (long)b * TT * NKC;

    // ---------------- init ----------------
    for (int idx = tid; idx < NREC * NREC; idx += NTHREADS) {
        int i = idx / NREC, j = idx % NREC;
        float v = W_recur[idx];
        if (i < NMBON && j >= NREC - NDAN) v = 0.f;
        WrM[idx] = v;
    }
    if (tid < NREC)  bias_s[tid] = bias[tid];
    if (tid < NMBON) wro_s[tid]  = W_readout[tid];
    if (tid >= 128 && tid < 128 + NFBN * 2) wext_s[tid - 128] = W_ext[tid - 128];
    if (tid < NREC) {
        float r0 = (tid < NMBON) ? 0.f : 0.1f;
        r_s[tid] = r0;
        out_r[(long)b * NREC + tid] = r0;
    }
    for (int k = tid; k < NKC; k += NTHREADS)
        rkc3[k] = rkc_g[k];               // ring slot 0 = rkc(0)
    __syncthreads();                      // wext ready
    if (tid < NFBN) {
        float e0 = r_ext[((long)b * 2 + 0) * TT];
        float e1 = r_ext[((long)b * 2 + 1) * TT];
        ifbn[tid] = wext_s[tid * 2] * e0 + wext_s[tid * 2 + 1] * e1;
    }
    if (tid == 0) out_ro[b] = 0.f;

    // owner state: W, wt, rb_kc (registers)
    float4 Wv[10], wtv[10], bkv;
    if (owner) {
        const long ibase = ((long)b * NMBON + g * 10) * NKC + q * 4;
#pragma unroll
        for (int mm = 0; mm < 10; ++mm) {
            Wv[mm]  = *(const float4*)(W_kc0 + ibase + (long)mm * NKC);
            wtv[mm] = *(const float4*)(wt0   + ibase + (long)mm * NKC);
        }
        bkv = *(const float4*)(rkc_g + q * 4);   // rb_kc0 = rkc(:,0)
    } else {
#pragma unroll
        for (int mm = 0; mm < 10; ++mm) {
            Wv[mm]  = make_float4(0.f, 0.f, 0.f, 0.f);
            wtv[mm] = Wv[mm];
        }
        bkv = make_float4(0.f, 0.f, 0.f, 0.f);
    }
    float rb_reg = 0.1f;                  // rbdan carry (DAN h==0 lanes)
    __syncthreads();                      // r_s, rkc3[0] ready

    // ---------------- time loop ----------------
    int pcur = 0;
    for (int t = 0; t < NSTEP; ++t) {
        const int pnext = (pcur == 2) ? 0 : pcur + 1;
        const int hb = t & 1;
        const float* rc = r_s + hb * NREC;
        float* rn_buf   = r_s + (hb ^ 1) * NREC;

        // ============ pre-bar1 ============
        if (owner) {
            // B(t): I_mbon partials
            float4 kc = *(const float4*)(rkc3 + pcur * 800 + q * 4);
            if ((warp & 7) == 6) {
                // mixed warps: owners are lanes 0-7 only (q=192..199)
#pragma unroll
                for (int mm = 0; mm < 10; ++mm) {
                    float4 w = Wv[mm];
                    float p = w.x * kc.x + w.y * kc.y + w.z * kc.z + w.w * kc.w;
                    p += __shfl_xor_sync(0xFFu, p, 4);
                    p += __shfl_xor_sync(0xFFu, p, 2);
                    p += __shfl_xor_sync(0xFFu, p, 1);
                    if (lane == 0) red_s[6 * 20 + g * 10 + mm] = p;
                }
            } else {
#pragma unroll
                for (int mm = 0; mm < 10; ++mm) {
                    float4 w = Wv[mm];
                    float p = w.x * kc.x + w.y * kc.y + w.z * kc.z + w.w * kc.w;
                    p += __shfl_xor_sync(0xffffffffu, p, 16);
                    p += __shfl_xor_sync(0xffffffffu, p, 8);
                    p += __shfl_xor_sync(0xffffffffu, p, 4);
                    p += __shfl_xor_sync(0xffffffffu, p, 2);
                    p += __shfl_xor_sync(0xffffffffu, p, 1);
                    if (lane == 0) red_s[(warp & 7) * 20 + g * 10 + mm] = p;
                }
            }
        } else if (is_dan) {
            // DAN(t): r(t+1)[80..99], 2-way j-split (I_tot = 0 for DAN rows)
            const float4* wrow = (const float4*)(WrM + drow * NREC);
            const float4* r4   = (const float4*)rc;
            float a0 = 0.f, a1 = 0.f;
            const int base = dh * 13;     // h=0: jb 0..12 ; h=1: jb 13..24
#pragma unroll
            for (int jb = 0; jb < 13; ++jb) {
                int j = base + jb;
                if (j < 25) {
                    float4 wv = wrow[j];
                    float4 rv = r4[j];
                    a0 = fmaf(wv.x, rv.x, a0);
                    a1 = fmaf(wv.y, rv.y, a1);
                    a0 = fmaf(wv.z, rv.z, a0);
                    a1 = fmaf(wv.w, rv.w, a1);
                }
            }
            float p = a0 + a1;
            p += __shfl_xor_sync(dmask, p, 1);
            if (dh == 0) {
                float pre  = p + bias_s[drow];
                float rold = rc[drow];
                float rn   = fmaf(a_r, fmaxf(pre, 0.f) - rold, rold);
                rn_buf[drow] = rn;
                out_r[((long)(t + 1) * BB + b) * NREC + drow] = rn;
                int m = drow - 80;
                rdan_s[m] = rn;
                rb_reg = fmaf(a_w, rn - rb_reg, rb_reg);
                rbdan_s[m] = rb_reg;
            }
        } else if (is_stage) {
            // cp.async rkc(t+1) -> ring[pnext]; ifbn(t+1)
            const float* gsrc = rkc_g + (long)(t + 1) * NKC;
#pragma unroll
            for (int j = 0; j < 9; ++j) {
                int c = sl + 24 * j;
                if (c < 200) {
                    uint32_t dst = (uint32_t)__cvta_generic_to_shared(rkc3 + pnext * 800 + c * 4);
                    asm volatile("cp.async.cg.shared.global [%0], [%1], 16;\n"
                                 :: "r"(dst), "l"(gsrc + c * 4));
                }
            }
            asm volatile("cp.async.commit_group;\n" ::: "memory");
            float e0 = r_ext[((long)b * 2 + 0) * TT + (t + 1)];
            float e1 = r_ext[((long)b * 2 + 1) * TT + (t + 1)];
#pragma unroll
            for (int j = 0; j < 3; ++j) {
                int f = sl + 24 * j;
                if (f < NFBN)
                    ifbn[(hb ^ 1) * 64 + f] = wext_s[f * 2] * e0 + wext_s[f * 2 + 1] * e1;
            }
        } else if (tid == 456 && t > 0) {
            // readout(t) from r(t)
            float v = 0.f;
#pragma unroll
            for (int m = 0; m < NMBON; ++m)
                v = fmaf(rc[m], wro_s[m], v);
            out_ro[(long)t * BB + b] = v;
        }
        __syncthreads();   // bar1: red_s, rdan/rbdan(t), ifbn(t+1) ready

        // ============ post-bar1 ============
        if (owner) {
            // D(t): rb_kc EMA (registers) + plasticity compute (no stores)
            float4 kc = *(const float4*)(rkc3 + pcur * 800 + q * 4);
            bkv.x = fmaf(a_w, kc.x - bkv.x, bkv.x);
            bkv.y = fmaf(a_w, kc.y - bkv.y, bkv.y);
            bkv.z = fmaf(a_w, kc.z - bkv.z, bkv.z);
            bkv.w = fmaf(a_w, kc.w - bkv.w, bkv.w);
#pragma unroll
            for (int mm = 0; mm < 10; ++mm) {
                const int m = g * 10 + mm;
                const float rbd = rbdan_s[m];
                const float rd  = rdan_s[m];
                float4 w = Wv[mm], wt = wtv[mm];
                float dw;
                dw = fmaf(rbd, kc.x, -(rd * bkv.x)); wt.x = fmaf(dw, dt, wt.x);
                dw = fmaf(rbd, kc.y, -(rd * bkv.y)); wt.y = fmaf(dw, dt, wt.y);
                dw = fmaf(rbd, kc.z, -(rd * bkv.z)); wt.z = fmaf(dw, dt, wt.z);
                dw = fmaf(rbd, kc.w, -(rd * bkv.w)); wt.w = fmaf(dw, dt, wt.w);
                w.x = fminf(fmaxf(fmaf(a_w, wt.x - w.x, w.x), 0.f), W_MAXC);
                w.y = fminf(fmaxf(fmaf(a_w, wt.y - w.y, w.y), 0.f), W_MAXC);
                w.z = fminf(fmaxf(fmaf(a_w, wt.z - w.z, w.z), 0.f), W_MAXC);
                w.w = fminf(fmaxf(fmaf(a_w, wt.w - w.w, w.w), 0.f), W_MAXC);
                Wv[mm] = w; wtv[mm] = wt;
            }
        } else {
            if (di >= 0) {
                // MBON/FBN r-update for i = di
                const float4* wrow = (const float4*)(WrM + di * NREC);
                const float4* r4   = (const float4*)rc;
                float a0 = 0.f, a1 = 0.f, a2 = 0.f, a3 = 0.f;
#pragma unroll
                for (int jb = 0; jb < 25; ++jb) {
                    float4 wv = wrow[jb];
                    float4 rv = r4[jb];
                    a0 = fmaf(wv.x, rv.x, a0);
                    a1 = fmaf(wv.y, rv.y, a1);
                    a2 = fmaf(wv.z, rv.z, a2);
                    a3 = fmaf(wv.w, rv.w, a3);
                }
                float p = (a0 + a1) + (a2 + a3);
                float itot;
                if (di < NMBON) {
                    float s0 = red_s[0 * 20 + di] + red_s[1 * 20 + di];
                    float s1 = red_s[2 * 20 + di] + red_s[3 * 20 + di];
                    float s2 = red_s[4 * 20 + di] + red_s[5 * 20 + di];
                    itot = (s0 + s1) + (s2 + red_s[6 * 20 + di]);
                } else {
                    itot = ifbn[hb * 64 + (di - NMBON)];
                }
                float pre  = p + bias_s[di] + itot;
                float rold = rc[di];
                float rn   = fmaf(a_r, fmaxf(pre, 0.f) - rold, rold);
                rn_buf[di] = rn;
                out_r[((long)(t + 1) * BB + b) * NREC + di] = rn;
            }
            if (is_stage)
                asm volatile("cp.async.wait_group 0;\n" ::: "memory");
        }
        __syncthreads();   // bar2: r(t+1) complete, ring[pnext] ready
        pcur = pnext;
    }

    // final readout: t = 120, r(120) is in buffer 0
    if (tid == 456) {
        float v = 0.f;
#pragma unroll
        for (int m = 0; m < NMBON; ++m)
            v = fmaf(r_s[m], wro_s[m], v);
        out_ro[(long)NSTEP * BB + b] = v;
    }
}

// ---------------------------------------------------------------------------
// PASS 2: plasticity streaming (unchanged from R9, proven).
// grid (5, 48), 256 threads (q<200 active). Thread owns (b, 4 m-rows, k-chunk),
// walks t in registers, bit-identical FMA sequences, coalesced STG.128.
// ---------------------------------------------------------------------------
__global__ __launch_bounds__(256) void plast_kernel(
    const float* __restrict__ time_arr,
    const float* __restrict__ W_kc0,
    const float* __restrict__ wt0,
    float* __restrict__ out)
{
    const int q  = threadIdx.x;
    if (q >= 200) return;
    const int mg = blockIdx.x;
    const int b  = blockIdx.y;
    const int m0 = mg * 4;

    const float* out_r  = out;
    float* out_W  = out + (long)TT * BB * NREC;
    float* out_wt = out_W + (long)TT * BB * NMBON * NKC;

    const float dt  = time_arr[1] - time_arr[0];
    const float a_w = dt * 0.2f;

    const float* rkc_g = g_rkcT + (long)b * TT * NKC;

    float4 W[4], wt[4];
    float  rb[4];
    {
        const long ib  = ((long)b * NMBON + m0) * NKC + q * 4;
        const long ob0 = ((long)b) * (NMBON * NKC) + (long)m0 * NKC + q * 4;
#pragma unroll
        for (int mm = 0; mm < 4; ++mm) {
            W[mm]  = *(const float4*)(W_kc0 + ib + (long)mm * NKC);
            wt[mm] = *(const float4*)(wt0   + ib + (long)mm * NKC);
            *(float4*)(out_W  + ob0 + (long)mm * NKC) = W[mm];
            *(float4*)(out_wt + ob0 + (long)mm * NKC) = wt[mm];
            rb[mm] = 0.1f;
        }
    }
    float4 bk = *(const float4*)(rkc_g + q * 4);

    float4 kc = bk;
    float  rdn[4];
#pragma unroll
    for (int mm = 0; mm < 4; ++mm)
        rdn[mm] = out_r[((long)1 * BB + b) * NREC + 80 + m0 + mm];

    for (int t = 0; t < NSTEP; ++t) {
        float4 kc_n = kc;
        float  rdn_n[4];
        if (t + 1 < NSTEP) {
            kc_n = *(const float4*)(rkc_g + (long)(t + 1) * NKC + q * 4);
#pragma unroll
            for (int mm = 0; mm < 4; ++mm)
                rdn_n[mm] = out_r[((long)(t + 2) * BB + b) * NREC + 80 + m0 + mm];
        }

        bk.x = fmaf(a_w, kc.x - bk.x, bk.x);
        bk.y = fmaf(a_w, kc.y - bk.y, bk.y);
        bk.z = fmaf(a_w, kc.z - bk.z, bk.z);
        bk.w = fmaf(a_w, kc.w - bk.w, bk.w);

        const long ob = ((long)(t + 1) * BB + b) * (NMBON * NKC) + (long)m0 * NKC + q * 4;
#pragma unroll
        for (int mm = 0; mm < 4; ++mm) {
            const float rd = rdn[mm];
            rb[mm] = fmaf(a_w, rd - rb[mm], rb[mm]);
            const float rbd = rb[mm];
            float4 w = W[mm], wv = wt[mm];
            float dw;
            dw = fmaf(rbd, kc.x, -(rd * bk.x)); wv.x = fmaf(dw, dt, wv.x);
            dw = fmaf(rbd, kc.y, -(rd * bk.y)); wv.y = fmaf(dw, dt, wv.y);
            dw = fmaf(rbd, kc.z, -(rd * bk.z)); wv.z = fmaf(dw, dt, wv.z);
            dw = fmaf(rbd, kc.w, -(rd * bk.w)); wv.w = fmaf(dw, dt, wv.w);
            w.x = fminf(fmaxf(fmaf(a_w, wv.x - w.x, w.x), 0.f), W_MAXC);
            w.y = fminf(fmaxf(fmaf(a_w, wv.y - w.y, w.y), 0.f), W_MAXC);
            w.z = fminf(fmaxf(fmaf(a_w, wv.z - w.z, w.z), 0.f), W_MAXC);
            w.w = fminf(fmaxf(fmaf(a_w, wv.w - w.w, w.w), 0.f), W_MAXC);
            W[mm] = w; wt[mm] = wv;
            *(float4*)(out_W  + ob + (long)mm * NKC) = w;
            *(float4*)(out_wt + ob + (long)mm * NKC) = wv;
        }

        kc = kc_n;
#pragma unroll
        for (int mm = 0; mm < 4; ++mm) rdn[mm] = rdn_n[mm];
    }
}

// ---------------------------------------------------------------------------
extern "C" void kernel_launch(void* const* d_in, const int* in_sizes, int n_in,
                              void* d_out, int out_size) {
    const float* r_kc      = (const float*)d_in[0];
    const float* r_ext     = (const float*)d_in[1];
    const float* time_arr  = (const float*)d_in[2];
    const float* W_kc0     = (const float*)d_in[3];
    const float* wt0       = (const float*)d_in[4];
    const float* W_recur   = (const float*)d_in[5];
    const float* W_readout = (const float*)d_in[6];
    const float* bias      = (const float*)d_in[7];
    const float* W_ext     = (const float*)d_in[8];
    float* out = (float*)d_out;

    cudaFuncSetAttribute(rnn_kernel, cudaFuncAttributeMaxDynamicSharedMemorySize,
                         SM_FLOATS * (int)sizeof(float));

    transpose_kernel<<<dim3(4, 25, BB), dim3(32, 32)>>>(r_kc);
    rnn_kernel<<<BB, NTHREADS, SM_FLOATS * (int)sizeof(float)>>>(
        r_ext, time_arr, W_kc0, wt0, W_recur, W_readout, bias, W_ext, out);
    plast_kernel<<<dim3(5, BB), 256>>>(time_arr, W_kc0, wt0, out);
}

// round 11
// speedup vs baseline: 1.4861x; 1.4861x over previous
#include <cuda_runtime.h>
#include <cstdint>

#define BB      48
#define NKC     800
#define NMBON   20
#define NFBN    60
#define NDAN    20
#define NREC    100
#define TT      121
#define NSTEP   120
#define W_MAXC  0.05f

#define NTHREADS 512
#define NCTA     (BB * 2)

__device__ float g_rkcT[(long)BB * TT * NKC];

// ---------------------------------------------------------------------------
// Transpose r_kc [B, NKC, T] -> g_rkcT [B, T, NKC]
// ---------------------------------------------------------------------------
__global__ void transpose_kernel(const float* __restrict__ rkc) {
    __shared__ float tile[32][33];
    const int bz = blockIdx.z;
    const int kt = blockIdx.y;
    const int tt = blockIdx.x;
    const int tx = threadIdx.x, ty = threadIdx.y;

    int k = kt * 32 + ty;
    int t = tt * 32 + tx;
    if (t < TT)
        tile[ty][tx] = rkc[((long)bz * NKC + k) * TT + t];
    __syncthreads();
    int t2 = tt * 32 + ty;
    int k2 = kt * 32 + tx;
    if (t2 < TT)
        g_rkcT[((long)bz * TT + t2) * NKC + k2] = tile[tx][ty];
}

// ---------------------------------------------------------------------------
// R7 structure (best: 313us) + ring-4 distance-2 rkc prefetch + rb_kc in
// owner registers. Cluster of 2 CTAs per batch (m-split), 512 threads.
// Owners: q=tid&255<200, g=tid>>8 -> rows m_off+g*5+0..4, chunk q.
// Warp 7: DAN-C pre-bar1; post-bar1 lanes 0-9 send+local-mbon, 10-19
//   peer-mbon (wait), 20-31 fbn 20-31.
// Warp 15: cp.async prefetch (distance 2) + ifbn pre-bar1; lanes 0-23 fbn
//   dots 32-55 post-bar1 + wait_group 1.
// Warp 6 lanes 8-19: fbn 56-67. Warp 14 lanes 8-19: fbn 68-79.
// ---------------------------------------------------------------------------
// smem floats: mbar 4 | imb 40 | WrM 10000 | rkc4 3200 | r 200 | bias 100 |
//              ifbn 128 | red 80 | rdan 20 | rbdan 20 | wro 20 | wext 120
#define SM_FLOATS (4 + 40 + 10000 + 3200 + 200 + 100 + 128 + 80 + 20 + 20 + 20 + 120)

__global__ __launch_bounds__(NTHREADS, 1) __cluster_dims__(2, 1, 1)
void rnn_kernel(
    const float* __restrict__ r_ext,
    const float* __restrict__ time_arr,
    const float* __restrict__ W_kc0,
    const float* __restrict__ wt0,
    const float* __restrict__ W_recur,
    const float* __restrict__ W_readout,
    const float* __restrict__ bias,
    const float* __restrict__ W_ext,
    float* __restrict__ out)
{
    extern __shared__ float sm[];
    float* mbar_f  = sm;                  // 4
    float* imb     = sm + 4;              // 2 x 20
    float* WrM     = sm + 44;             // 100 x 100 row-major
    float* rkc4    = sm + 10044;          // 4 x 800 ring
    float* r_s     = sm + 13244;          // 2 x 100
    float* bias_s  = sm + 13444;          // 100
    float* ifbn    = sm + 13544;          // 2 x 64
    float* red_s   = sm + 13672;          // 8 slots x 10 (slot 7 stays 0)
    float* rdan_s  = sm + 13752;          // 20
    float* rbdan_s = sm + 13772;          // 20
    float* wro_s   = sm + 13792;          // 20
    float* wext_s  = sm + 13812;          // 120

    const int tid  = threadIdx.x;
    const int bx   = blockIdx.x;
    const int b    = bx >> 1;
    const int rank = bx & 1;
    const int prank = rank ^ 1;
    const int m_off = rank * 10;
    const int lane = tid & 31;
    const int warp = tid >> 5;
    const int g    = tid >> 8;
    const int q    = tid & 255;
    const bool owner = (q < 200);

    int ci2 = -1;
    bool is_loc = false, is_peer = false;
    if (warp == 7) {
        if (lane < 10)      { ci2 = m_off + lane;            is_loc  = true; }
        else if (lane < 20) { ci2 = (m_off ^ 10) + lane - 10; is_peer = true; }
        else                { ci2 = 20 + (lane - 20); }
    } else if (warp == 15) {
        if (lane < 24) ci2 = 32 + lane;
    } else if (warp == 6) {
        if (lane >= 8 && lane < 20) ci2 = 56 + (lane - 8);
    } else if (warp == 14) {
        if (lane >= 8 && lane < 20) ci2 = 68 + (lane - 8);
    }

    float* out_r  = out;
    float* out_W  = out + (long)TT * BB * NREC;
    float* out_wt = out_W + (long)TT * BB * NMBON * NKC;
    float* out_ro = out_wt + (long)TT * BB * NMBON * NKC;

    const float dt  = time_arr[1] - time_arr[0];
    const float a_r = dt;
    const float a_w = dt * 0.2f;

    const float* rkc_g = g_rkcT + (long)b * TT * NKC;

    const uint32_t imb_loc  = (uint32_t)__cvta_generic_to_shared(imb);
    const uint32_t mbar_loc = (uint32_t)__cvta_generic_to_shared(mbar_f);
    uint32_t imb_rem, mbar_rem;
    asm("mapa.shared::cluster.u32 %0, %1, %2;" : "=r"(imb_rem)  : "r"(imb_loc),  "r"(prank));
    asm("mapa.shared::cluster.u32 %0, %1, %2;" : "=r"(mbar_rem) : "r"(mbar_loc), "r"(prank));

    // ---------------- init ----------------
    if (tid == 0) {
        asm volatile("mbarrier.init.shared.b64 [%0], 10;" :: "r"(mbar_loc)     : "memory");
        asm volatile("mbarrier.init.shared.b64 [%0], 10;" :: "r"(mbar_loc + 8) : "memory");
    }
    for (int idx = tid; idx < NREC * NREC; idx += NTHREADS) {
        int i = idx / NREC, j = idx % NREC;
        float v = W_recur[idx];
        if (i < NMBON && j >= NREC - NDAN) v = 0.f;
        WrM[idx] = v;
    }
    if (tid < 80)       red_s[tid] = 0.f;
    if (tid < NREC)     bias_s[tid] = bias[tid];
    if (tid < NMBON)    wro_s[tid]  = W_readout[tid];
    if (tid >= 128 && tid < 128 + NFBN * 2) wext_s[tid - 128] = W_ext[tid - 128];
    if (tid < NREC) {
        float r0 = (tid < NMBON) ? 0.f : 0.1f;
        r_s[tid] = r0;
        if (rank == 0) out_r[(long)b * NREC + tid] = r0;
    }
    if (tid < NDAN) rbdan_s[tid] = 0.1f;
    for (int k = tid; k < NKC; k += NTHREADS)
        rkc4[k] = rkc_g[k];               // slot 0 = rkc(0)
    __syncthreads();                      // wext ready
    if (tid < NFBN) {
        float e0 = r_ext[((long)b * 2 + 0) * TT];
        float e1 = r_ext[((long)b * 2 + 1) * TT];
        ifbn[tid] = wext_s[tid * 2] * e0 + wext_s[tid * 2 + 1] * e1;
    }
    if (tid == 0 && rank == 0) out_ro[b] = 0.f;

    // owner state: W, wt, rb_kc (registers)
    float4 Wv[5], wtv[5], bkv;
    if (owner) {
        const long ibase = ((long)b * NMBON + m_off + g * 5) * NKC + q * 4;
        const long obase = ((long)b) * (NMBON * NKC) + (long)(m_off + g * 5) * NKC + q * 4;
#pragma unroll
        for (int mm = 0; mm < 5; ++mm) {
            float4 w  = *(const float4*)(W_kc0 + ibase + (long)mm * NKC);
            float4 wt = *(const float4*)(wt0   + ibase + (long)mm * NKC);
            Wv[mm] = w; wtv[mm] = wt;
            *(float4*)(out_W  + obase + (long)mm * NKC) = w;
            *(float4*)(out_wt + obase + (long)mm * NKC) = wt;
        }
        bkv = *(const float4*)(rkc_g + q * 4);   // rb_kc(-1) = rkc(:,0)
    } else {
#pragma unroll
        for (int mm = 0; mm < 5; ++mm) {
            Wv[mm]  = make_float4(0.f, 0.f, 0.f, 0.f);
            wtv[mm] = Wv[mm];
        }
        bkv = make_float4(0.f, 0.f, 0.f, 0.f);
    }

    // preloop prefetch: rkc(1) -> slot 1 (one committed group)
    if (warp == 15) {
        const float* gsrc = rkc_g + (long)1 * NKC;
#pragma unroll
        for (int j = 0; j < 7; ++j) {
            int c = lane + 32 * j;
            if (c < 200) {
                uint32_t dst = (uint32_t)__cvta_generic_to_shared(rkc4 + 800 + c * 4);
                asm volatile("cp.async.cg.shared.global [%0], [%1], 16;\n"
                             :: "r"(dst), "l"(gsrc + c * 4));
            }
        }
        asm volatile("cp.async.commit_group;\n" ::: "memory");
    }
    __syncthreads();
    asm volatile("barrier.cluster.arrive.aligned;" ::: "memory");
    asm volatile("barrier.cluster.wait.aligned;"   ::: "memory");

    // ---------------- time loop ----------------
    for (int t = 0; t < NSTEP; ++t) {
        const int s0  = t & 3;            // ring slot for rkc(t)
        const int hb  = t & 1;
        const int par = (t >> 1) & 1;

        const float* rc = r_s + hb * NREC;
        float* rn_buf   = r_s + (hb ^ 1) * NREC;

        // pre-bar1: B ∥ DAN-C (warp7) ∥ prefetch+ifbn (warp15)
        if ((warp & 7) != 7) {
            float4 kc = make_float4(0.f, 0.f, 0.f, 0.f);
            if (owner) kc = *(const float4*)(rkc4 + s0 * 800 + q * 4);
#pragma unroll
            for (int mm = 0; mm < 5; ++mm) {
                float4 w = Wv[mm];
                float p = w.x * kc.x + w.y * kc.y + w.z * kc.z + w.w * kc.w;
                p += __shfl_xor_sync(0xffffffffu, p, 16);
                p += __shfl_xor_sync(0xffffffffu, p, 8);
                p += __shfl_xor_sync(0xffffffffu, p, 4);
                p += __shfl_xor_sync(0xffffffffu, p, 2);
                p += __shfl_xor_sync(0xffffffffu, p, 1);
                if (lane == 0)
                    red_s[(warp & 7) * 10 + g * 5 + mm] = p;
            }
        } else if (warp == 7) {
            if (lane < NDAN) {
                const int i = 80 + lane;
                const float4* wrow = (const float4*)(WrM + i * NREC);
                const float4* r4   = (const float4*)rc;
                float a0 = 0.f, a1 = 0.f, a2 = 0.f, a3 = 0.f;
#pragma unroll
                for (int jb = 0; jb < 25; ++jb) {
                    float4 wv = wrow[jb];
                    float4 rv = r4[jb];
                    a0 = fmaf(wv.x, rv.x, a0);
                    a1 = fmaf(wv.y, rv.y, a1);
                    a2 = fmaf(wv.z, rv.z, a2);
                    a3 = fmaf(wv.w, rv.w, a3);
                }
                float pre  = (a0 + a1) + (a2 + a3) + bias_s[i];
                float relu = fmaxf(pre, 0.f);
                float rold = rc[i];
                float rn   = fmaf(a_r, relu - rold, rold);
                rn_buf[i] = rn;
                if (rank == 0) out_r[((long)(t + 1) * BB + b) * NREC + i] = rn;
                rdan_s[lane] = rn;
                float rb = rbdan_s[lane];
                rbdan_s[lane] = fmaf(a_w, rn - rb, rb);
            }
        } else {
            // warp 15: distance-2 prefetch rkc(t+2) -> slot (t+2)&3, then ifbn(t+1)
            if (t + 2 <= NSTEP - 1) {
                const float* gsrc = rkc_g + (long)(t + 2) * NKC;
                const int sw = (t + 2) & 3;
#pragma unroll
                for (int j = 0; j < 7; ++j) {
                    int c = lane + 32 * j;
                    if (c < 200) {
                        uint32_t dst = (uint32_t)__cvta_generic_to_shared(rkc4 + sw * 800 + c * 4);
                        asm volatile("cp.async.cg.shared.global [%0], [%1], 16;\n"
                                     :: "r"(dst), "l"(gsrc + c * 4));
                    }
                }
            }
            asm volatile("cp.async.commit_group;\n" ::: "memory");   // possibly empty
            float e0 = r_ext[((long)b * 2 + 0) * TT + (t + 1)];
            float e1 = r_ext[((long)b * 2 + 1) * TT + (t + 1)];
            {
                int f = lane;
                ifbn[(hb ^ 1) * 64 + f] = wext_s[f * 2] * e0 + wext_s[f * 2 + 1] * e1;
                f = lane + 32;
                if (f < NFBN)
                    ifbn[(hb ^ 1) * 64 + f] = wext_s[f * 2] * e0 + wext_s[f * 2 + 1] * e1;
            }
        }
        __syncthreads();   // bar1: red_s, rdan/rbdan(t), ifbn(t+1) ready

        // post-bar1: send FIRST, then D (owners) ∥ C dots ∥ cp wait
        float vloc = 0.f;
        if (warp == 7 && lane < 10) {
            vloc = red_s[0 * 10 + lane] + red_s[1 * 10 + lane] + red_s[2 * 10 + lane]
                 + red_s[3 * 10 + lane] + red_s[4 * 10 + lane] + red_s[5 * 10 + lane]
                 + red_s[6 * 10 + lane];
            asm volatile("st.shared::cluster.f32 [%0], %1;"
                         :: "r"(imb_rem + (hb * 20 + m_off + lane) * 4), "f"(vloc) : "memory");
            asm volatile("mbarrier.arrive.release.cluster.shared::cluster.b64 _, [%0];"
                         :: "r"(mbar_rem + hb * 8) : "memory");
        }

        if (owner) {
            // D(t): rb_kc EMA in registers + plasticity + streaming stores
            float4 kc = *(const float4*)(rkc4 + s0 * 800 + q * 4);
            bkv.x = fmaf(a_w, kc.x - bkv.x, bkv.x);
            bkv.y = fmaf(a_w, kc.y - bkv.y, bkv.y);
            bkv.z = fmaf(a_w, kc.z - bkv.z, bkv.z);
            bkv.w = fmaf(a_w, kc.w - bkv.w, bkv.w);
            const long obase = ((long)(t + 1) * BB + b) * (NMBON * NKC)
                             + (long)(m_off + g * 5) * NKC + q * 4;
#pragma unroll
            for (int mm = 0; mm < 5; ++mm) {
                const int m = m_off + g * 5 + mm;
                const float rbd = rbdan_s[m];
                const float rd  = rdan_s[m];
                float4 w = Wv[mm], wt = wtv[mm];
                float dw;
                dw = fmaf(rbd, kc.x, -(rd * bkv.x)); wt.x = fmaf(dw, dt, wt.x);
                dw = fmaf(rbd, kc.y, -(rd * bkv.y)); wt.y = fmaf(dw, dt, wt.y);
                dw = fmaf(rbd, kc.z, -(rd * bkv.z)); wt.z = fmaf(dw, dt, wt.z);
                dw = fmaf(rbd, kc.w, -(rd * bkv.w)); wt.w = fmaf(dw, dt, wt.w);
                w.x = fminf(fmaxf(fmaf(a_w, wt.x - w.x, w.x), 0.f), W_MAXC);
                w.y = fminf(fmaxf(fmaf(a_w, wt.y - w.y, w.y), 0.f), W_MAXC);
                w.z = fminf(fmaxf(fmaf(a_w, wt.z - w.z, w.z), 0.f), W_MAXC);
                w.w = fminf(fmaxf(fmaf(a_w, wt.w - w.w, w.w), 0.f), W_MAXC);
                Wv[mm] = w; wtv[mm] = wt;
                *(float4*)(out_W  + obase + (long)mm * NKC) = w;
                *(float4*)(out_wt + obase + (long)mm * NKC) = wt;
            }
        }

        if (ci2 >= 0) {
            const int i = ci2;
            const float4* wrow = (const float4*)(WrM + i * NREC);
            const float4* r4   = (const float4*)rc;
            float a0 = 0.f, a1 = 0.f, a2 = 0.f, a3 = 0.f;
#pragma unroll
            for (int jb = 0; jb < 25; ++jb) {
                float4 wv = wrow[jb];
                float4 rv = r4[jb];
                a0 = fmaf(wv.x, rv.x, a0);
                a1 = fmaf(wv.y, rv.y, a1);
                a2 = fmaf(wv.z, rv.z, a2);
                a3 = fmaf(wv.w, rv.w, a3);
            }
            float p = (a0 + a1) + (a2 + a3);
            float itot;
            if (is_loc) {
                itot = vloc;
            } else if (is_peer) {
                uint32_t done;
                asm volatile(
                    "{\n\t.reg .pred p;\n\t"
                    "mbarrier.try_wait.parity.acquire.cluster.shared::cta.b64 p, [%1], %2;\n\t"
                    "selp.b32 %0, 1, 0, p;\n\t}"
                    : "=r"(done) : "r"(mbar_loc + hb * 8), "r"(par) : "memory");
                while (!done) {
                    asm volatile(
                        "{\n\t.reg .pred p;\n\t"
                        "mbarrier.try_wait.parity.acquire.cluster.shared::cta.b64 p, [%1], %2, 0x989680;\n\t"
                        "selp.b32 %0, 1, 0, p;\n\t}"
                        : "=r"(done) : "r"(mbar_loc + hb * 8), "r"(par) : "memory");
                }
                itot = imb[hb * 20 + i];
            } else {
                itot = ifbn[hb * 64 + (i - NMBON)];
            }
            float pre  = p + bias_s[i] + itot;
            float relu = fmaxf(pre, 0.f);
            float rold = rc[i];
            float rn   = fmaf(a_r, relu - rold, rold);
            rn_buf[i] = rn;
            if (rank == 0) out_r[((long)(t + 1) * BB + b) * NREC + i] = rn;
        }

        if (warp == 15)
            asm volatile("cp.async.wait_group 1;\n" ::: "memory");   // rkc(t+1) ready

        __syncthreads();   // bar2

        if (warp == 0 && rank == 0) {
            float v = (lane < NMBON) ? rn_buf[lane] * wro_s[lane] : 0.f;
            v += __shfl_xor_sync(0xffffffffu, v, 16);
            v += __shfl_xor_sync(0xffffffffu, v, 8);
            v += __shfl_xor_sync(0xffffffffu, v, 4);
            v += __shfl_xor_sync(0xffffffffu, v, 2);
            v += __shfl_xor_sync(0xffffffffu, v, 1);
            if (lane == 0) out_ro[(long)(t + 1) * BB + b] = v;
        }
    }

    asm volatile("barrier.cluster.arrive.aligned;" ::: "memory");
    asm volatile("barrier.cluster.wait.aligned;"   ::: "memory");
}

// ---------------------------------------------------------------------------
extern "C" void kernel_launch(void* const* d_in, const int* in_sizes, int n_in,
                              void* d_out, int out_size) {
    const float* r_kc      = (const float*)d_in[0];
    const float* r_ext     = (const float*)d_in[1];
    const float* time_arr  = (const float*)d_in[2];
    const float* W_kc0     = (const float*)d_in[3];
    const float* wt0       = (const float*)d_in[4];
    const float* W_recur   = (const float*)d_in[5];
    const float* W_readout = (const float*)d_in[6];
    const float* bias      = (const float*)d_in[7];
    const float* W_ext     = (const float*)d_in[8];
    float* out = (float*)d_out;

    cudaFuncSetAttribute(rnn_kernel, cudaFuncAttributeMaxDynamicSharedMemorySize,
                         SM_FLOATS * (int)sizeof(float));

    transpose_kernel<<<dim3(4, 25, BB), dim3(32, 32)>>>(r_kc);
    rnn_kernel<<<NCTA, NTHREADS, SM_FLOATS * (int)sizeof(float)>>>(
        r_ext, time_arr, W_kc0, wt0, W_recur, W_readout, bias, W_ext, out);
}